// round 1
// baseline (speedup 1.0000x reference)
#include <cuda_runtime.h>

// ConvGRU cell, fully fused, one thread per pixel.
// All seven 32x32 matvecs done with packed fma.rn.f32x2 (FFMA2), accumulators
// packed over output-channel pairs; weights transposed in shared memory and
// read as 16B broadcast LDS.

#define HW 65536        // 256*256
#define NB 8
#define NCH 32

typedef unsigned long long ull;

__device__ __forceinline__ ull pack2(float a, float b) {
    ull r;
    asm("mov.b64 %0, {%1, %2};" : "=l"(r) : "f"(a), "f"(b));
    return r;
}
__device__ __forceinline__ void unpack2(ull v, float& a, float& b) {
    asm("mov.b64 {%0, %1}, %2;" : "=f"(a), "=f"(b) : "l"(v));
}
__device__ __forceinline__ void ffma2(ull& d, ull a, ull b) {
    asm("fma.rn.f32x2 %0, %1, %2, %3;" : "=l"(d) : "l"(a), "l"(b), "l"(d));
}
__device__ __forceinline__ float sigmoidf_(float a) {
    a = fminf(fmaxf(a, -30.f), 30.f);
    float e = __expf(-a);
    return __fdividef(1.f, 1.f + e);
}
__device__ __forceinline__ float tanhf_(float a) {
    a = fminf(fmaxf(a, -15.f), 15.f);
    float e = __expf(-2.f * a);
    return (1.f - e) * __fdividef(1.f, 1.f + e);
}

__global__ void __launch_bounds__(128, 2) gru_fused_kernel(
    const float* __restrict__ x, const float* __restrict__ h,
    const float* __restrict__ w_xz, const float* __restrict__ b_xz,
    const float* __restrict__ w_hz, const float* __restrict__ b_hz,
    const float* __restrict__ w_xr, const float* __restrict__ b_xr,
    const float* __restrict__ w_hr, const float* __restrict__ b_hr,
    const float* __restrict__ w_c,  const float* __restrict__ b_c,
    const float* __restrict__ w_u,  const float* __restrict__ b_u,
    const float* __restrict__ w_o,  const float* __restrict__ b_o,
    float* __restrict__ out)
{
    // Transposed weights: wT[m][c][o] = W_m[o][c]. Rows are 128B, 16B aligned,
    // read as ulonglong2 -> {(w[o],w[o+1]),(w[o+2],w[o+3])} output-channel pairs.
    __shared__ __align__(16) float wT[7][32][32];
    __shared__ __align__(16) float bz_s[32], br_s[32], bc_s[32], by_s[32];

    const int tid = threadIdx.x;
    {
        const float* W0 = w_xz; const float* W1 = w_hz;
        const float* W2 = w_xr; const float* W3 = w_hr;
        const float* W4 = w_c;  const float* W5 = w_u;
        const float* W6 = w_o;
        for (int idx = tid; idx < 1024; idx += 128) {
            int o = idx & 31, c = idx >> 5;   // coalesced smem store, conflict-free
            wT[0][c][o] = W0[o * 32 + c];
            wT[1][c][o] = W1[o * 32 + c];
            wT[2][c][o] = W2[o * 32 + c];
            wT[3][c][o] = W3[o * 32 + c];
            wT[4][c][o] = W4[o * 32 + c];
            wT[5][c][o] = W5[o * 32 + c];
            wT[6][c][o] = W6[o * 32 + c];
        }
        if (tid < 32) {
            bz_s[tid] = b_xz[tid] + b_hz[tid];
            br_s[tid] = b_xr[tid] + b_hr[tid];
            bc_s[tid] = b_c[tid]  + b_u[tid];
            by_s[tid] = b_o[tid];
        }
    }
    __syncthreads();

    const int gp = blockIdx.x * 128 + tid;     // global pixel id, exactly covers 524288
    const int b  = gp >> 16;
    const int p  = gp & 65535;
    const float* xb = x + (b * 32) * HW + p;
    const float* hb = h + (b * 32) * HW + p;

    float xv[32], hv[32];
#pragma unroll
    for (int c = 0; c < 32; c++) { xv[c] = xb[c * HW]; hv[c] = hb[c * HW]; }

    // ---- Stage A: z_pre and r_pre (shared input loop over x and h) ----
    ull za[16], ra[16];
#pragma unroll
    for (int j = 0; j < 16; j++) {
        za[j] = pack2(bz_s[2 * j], bz_s[2 * j + 1]);
        ra[j] = pack2(br_s[2 * j], br_s[2 * j + 1]);
    }
#pragma unroll
    for (int c = 0; c < 32; c++) {
        ull xd = pack2(xv[c], xv[c]);
        ull hd = pack2(hv[c], hv[c]);
        const ulonglong2* rzx = (const ulonglong2*)&wT[0][c][0];
        const ulonglong2* rzh = (const ulonglong2*)&wT[1][c][0];
        const ulonglong2* rrx = (const ulonglong2*)&wT[2][c][0];
        const ulonglong2* rrh = (const ulonglong2*)&wT[3][c][0];
#pragma unroll
        for (int q = 0; q < 8; q++) {
            ulonglong2 w0 = rzx[q]; ffma2(za[2 * q], w0.x, xd); ffma2(za[2 * q + 1], w0.y, xd);
            ulonglong2 w1 = rzh[q]; ffma2(za[2 * q], w1.x, hd); ffma2(za[2 * q + 1], w1.y, hd);
            ulonglong2 w2 = rrx[q]; ffma2(ra[2 * q], w2.x, xd); ffma2(ra[2 * q + 1], w2.y, xd);
            ulonglong2 w3 = rrh[q]; ffma2(ra[2 * q], w3.x, hd); ffma2(ra[2 * q + 1], w3.y, hd);
        }
    }

    float zf[32], rv[32];   // z gate; rv = r_t * h (input to W_u)
#pragma unroll
    for (int j = 0; j < 16; j++) {
        float a0, a1, r0, r1;
        unpack2(za[j], a0, a1);
        unpack2(ra[j], r0, r1);
        zf[2 * j]     = sigmoidf_(a0);
        zf[2 * j + 1] = sigmoidf_(a1);
        rv[2 * j]     = sigmoidf_(r0) * hv[2 * j];
        rv[2 * j + 1] = sigmoidf_(r1) * hv[2 * j + 1];
    }

    // ---- Stage B: h_hat = tanh(W_c x + b_c + W_u (r*h) + b_u), then blend ----
    ull ca[16];
#pragma unroll
    for (int j = 0; j < 16; j++) ca[j] = pack2(bc_s[2 * j], bc_s[2 * j + 1]);
#pragma unroll
    for (int c = 0; c < 32; c++) {
        ull xd = pack2(xv[c], xv[c]);
        ull rd = pack2(rv[c], rv[c]);
        const ulonglong2* rc = (const ulonglong2*)&wT[4][c][0];
        const ulonglong2* ru = (const ulonglong2*)&wT[5][c][0];
#pragma unroll
        for (int q = 0; q < 8; q++) {
            ulonglong2 w0 = rc[q]; ffma2(ca[2 * q], w0.x, xd); ffma2(ca[2 * q + 1], w0.y, xd);
            ulonglong2 w1 = ru[q]; ffma2(ca[2 * q], w1.x, rd); ffma2(ca[2 * q + 1], w1.y, rd);
        }
    }

    float ht[32];
#pragma unroll
    for (int j = 0; j < 16; j++) {
        float c0, c1;
        unpack2(ca[j], c0, c1);
        float hh0 = tanhf_(c0), hh1 = tanhf_(c1);
        int o = 2 * j;
        ht[o]     = fmaf(zf[o],     hh0 - hv[o],     hv[o]);
        ht[o + 1] = fmaf(zf[o + 1], hh1 - hv[o + 1], hv[o + 1]);
    }

    // ---- Stage C: y = W_o h_t + b_o ----
    ull ya[16];
#pragma unroll
    for (int j = 0; j < 16; j++) ya[j] = pack2(by_s[2 * j], by_s[2 * j + 1]);
#pragma unroll
    for (int c = 0; c < 32; c++) {
        ull hd = pack2(ht[c], ht[c]);
        const ulonglong2* ro = (const ulonglong2*)&wT[6][c][0];
#pragma unroll
        for (int q = 0; q < 8; q++) {
            ulonglong2 w0 = ro[q]; ffma2(ya[2 * q], w0.x, hd); ffma2(ya[2 * q + 1], w0.y, hd);
        }
    }

    // ---- Stores: out = [ y (8,32,256,256) | h_t (8,32,256,256) ] ----
    float* yout = out + (b * 32) * HW + p;
    float* hout = out + NB * 32 * HW + (b * 32) * HW + p;
#pragma unroll
    for (int j = 0; j < 16; j++) {
        float y0, y1;
        unpack2(ya[j], y0, y1);
        yout[(2 * j) * HW]     = y0;
        yout[(2 * j + 1) * HW] = y1;
    }
#pragma unroll
    for (int o = 0; o < 32; o++) hout[o * HW] = ht[o];
}

extern "C" void kernel_launch(void* const* d_in, const int* in_sizes, int n_in,
                              void* d_out, int out_size) {
    const float* x    = (const float*)d_in[0];
    const float* h    = (const float*)d_in[1];
    const float* w_xz = (const float*)d_in[2];
    const float* b_xz = (const float*)d_in[3];
    const float* w_hz = (const float*)d_in[4];
    const float* b_hz = (const float*)d_in[5];
    const float* w_xr = (const float*)d_in[6];
    const float* b_xr = (const float*)d_in[7];
    const float* w_hr = (const float*)d_in[8];
    const float* b_hr = (const float*)d_in[9];
    const float* w_c  = (const float*)d_in[10];
    const float* b_c  = (const float*)d_in[11];
    const float* w_u  = (const float*)d_in[12];
    const float* b_u  = (const float*)d_in[13];
    const float* w_o  = (const float*)d_in[14];
    const float* b_o  = (const float*)d_in[15];
    float* out = (float*)d_out;

    // 524288 pixels / 128 threads = 4096 blocks, exact cover.
    gru_fused_kernel<<<4096, 128>>>(x, h,
                                    w_xz, b_xz, w_hz, b_hz,
                                    w_xr, b_xr, w_hr, b_hr,
                                    w_c, b_c, w_u, b_u,
                                    w_o, b_o, out);
}

// round 2
// speedup vs baseline: 1.3902x; 1.3902x over previous
#include <cuda_runtime.h>

// ConvGRU cell, fully fused, one thread per pixel.
// Weights live in __constant__ memory (separate const/uniform port) so the
// L1tex pipe only carries the pixel loads/stores. All matvecs use packed
// fma.rn.f32x2 with output-channel-pair accumulators.

#define HW 65536        // 256*256
#define NB 8

typedef unsigned long long ull;

// [m][c][o] transposed weights (7*1024 floats) followed by 4 combined bias
// vectors (bz, br, bc, by). One contiguous symbol -> one memcpy.
__constant__ __align__(16) float cAll[7 * 1024 + 4 * 32];
__device__   __align__(16) float g_stage[7 * 1024 + 4 * 32];

__device__ __forceinline__ ull pack2(float a, float b) {
    ull r;
    asm("mov.b64 %0, {%1, %2};" : "=l"(r) : "f"(a), "f"(b));
    return r;
}
__device__ __forceinline__ void unpack2(ull v, float& a, float& b) {
    asm("mov.b64 {%0, %1}, %2;" : "=f"(a), "=f"(b) : "l"(v));
}
__device__ __forceinline__ void ffma2(ull& d, ull a, ull b) {
    asm("fma.rn.f32x2 %0, %1, %2, %3;" : "=l"(d) : "l"(a), "l"(b), "l"(d));
}
__device__ __forceinline__ float sigmoidf_(float a) {
    a = fminf(fmaxf(a, -30.f), 30.f);
    float e = __expf(-a);
    return __fdividef(1.f, 1.f + e);
}
__device__ __forceinline__ float tanhf_(float a) {
    a = fminf(fmaxf(a, -15.f), 15.f);
    float e = __expf(-2.f * a);
    return (1.f - e) * __fdividef(1.f, 1.f + e);
}

__global__ void prep_kernel(
    const float* __restrict__ w_xz, const float* __restrict__ w_hz,
    const float* __restrict__ w_xr, const float* __restrict__ w_hr,
    const float* __restrict__ w_c,  const float* __restrict__ w_u,
    const float* __restrict__ w_o,
    const float* __restrict__ b_xz, const float* __restrict__ b_hz,
    const float* __restrict__ b_xr, const float* __restrict__ b_hr,
    const float* __restrict__ b_c,  const float* __restrict__ b_u,
    const float* __restrict__ b_o)
{
    int t = threadIdx.x;               // 1024 threads
    int o = t & 31, c = t >> 5;
    // transpose W[o][c] -> stage[m][c][o]
    g_stage[0 * 1024 + c * 32 + o] = w_xz[o * 32 + c];
    g_stage[1 * 1024 + c * 32 + o] = w_hz[o * 32 + c];
    g_stage[2 * 1024 + c * 32 + o] = w_xr[o * 32 + c];
    g_stage[3 * 1024 + c * 32 + o] = w_hr[o * 32 + c];
    g_stage[4 * 1024 + c * 32 + o] = w_c [o * 32 + c];
    g_stage[5 * 1024 + c * 32 + o] = w_u [o * 32 + c];
    g_stage[6 * 1024 + c * 32 + o] = w_o [o * 32 + c];
    if (t < 32) {
        g_stage[7168 +  0 + t] = b_xz[t] + b_hz[t];
        g_stage[7168 + 32 + t] = b_xr[t] + b_hr[t];
        g_stage[7168 + 64 + t] = b_c[t]  + b_u[t];
        g_stage[7168 + 96 + t] = b_o[t];
    }
}

// One matvec sweep: acc[16] (ull pairs over output channels) += W_m * invec.
// Inner body touches exactly 4KB of constant space -> const-cache friendly.
#define SWEEP(acc, m, invec)                                                   \
    _Pragma("unroll")                                                          \
    for (int c = 0; c < 32; c++) {                                             \
        ull d = pack2((invec)[c], (invec)[c]);                                 \
        const ulonglong2* row = (const ulonglong2*)&cAll[(m) * 1024 + c * 32]; \
        _Pragma("unroll")                                                      \
        for (int q = 0; q < 8; q++) {                                          \
            ulonglong2 w = row[q];                                             \
            ffma2((acc)[2 * q], w.x, d);                                       \
            ffma2((acc)[2 * q + 1], w.y, d);                                   \
        }                                                                      \
    }

__global__ void __launch_bounds__(128, 2) gru_fused_kernel(
    const float* __restrict__ x, const float* __restrict__ h,
    float* __restrict__ out)
{
    const int gp = blockIdx.x * 128 + threadIdx.x;   // covers 524288 exactly
    const int b  = gp >> 16;
    const int p  = gp & 65535;
    const float* xb = x + (b * 32) * HW + p;
    const float* hb = h + (b * 32) * HW + p;

    float xv[32], hv[32];
#pragma unroll
    for (int c = 0; c < 32; c++) { xv[c] = xb[c * HW]; hv[c] = hb[c * HW]; }

    const float* bz_c = &cAll[7168];
    const float* br_c = &cAll[7168 + 32];
    const float* bc_c = &cAll[7168 + 64];
    const float* by_c = &cAll[7168 + 96];

    // ---- z gate ----
    ull za[16];
#pragma unroll
    for (int j = 0; j < 16; j++) za[j] = pack2(bz_c[2 * j], bz_c[2 * j + 1]);
    SWEEP(za, 0, xv)   // W_xz * x
    SWEEP(za, 1, hv)   // W_hz * h

    // ---- r gate ----
    ull ra[16];
#pragma unroll
    for (int j = 0; j < 16; j++) ra[j] = pack2(br_c[2 * j], br_c[2 * j + 1]);
    SWEEP(ra, 2, xv)   // W_xr * x
    SWEEP(ra, 3, hv)   // W_hr * h

    float zf[32], rv[32];       // z gate; rv = r_t * h
#pragma unroll
    for (int j = 0; j < 16; j++) {
        float a0, a1, r0, r1;
        unpack2(za[j], a0, a1);
        unpack2(ra[j], r0, r1);
        zf[2 * j]     = sigmoidf_(a0);
        zf[2 * j + 1] = sigmoidf_(a1);
        rv[2 * j]     = sigmoidf_(r0) * hv[2 * j];
        rv[2 * j + 1] = sigmoidf_(r1) * hv[2 * j + 1];
    }

    // ---- candidate ----
    ull ca[16];
#pragma unroll
    for (int j = 0; j < 16; j++) ca[j] = pack2(bc_c[2 * j], bc_c[2 * j + 1]);
    SWEEP(ca, 4, xv)   // W_c * x
    SWEEP(ca, 5, rv)   // W_u * (r*h)

    float ht[32];
#pragma unroll
    for (int j = 0; j < 16; j++) {
        float c0, c1;
        unpack2(ca[j], c0, c1);
        float hh0 = tanhf_(c0), hh1 = tanhf_(c1);
        int o = 2 * j;
        ht[o]     = fmaf(zf[o],     hh0 - hv[o],     hv[o]);
        ht[o + 1] = fmaf(zf[o + 1], hh1 - hv[o + 1], hv[o + 1]);
    }

    // ---- output projection ----
    ull ya[16];
#pragma unroll
    for (int j = 0; j < 16; j++) ya[j] = pack2(by_c[2 * j], by_c[2 * j + 1]);
    SWEEP(ya, 6, ht)   // W_o * h_t

    // ---- stores: out = [ y (8,32,256,256) | h_t (8,32,256,256) ] ----
    float* yout = out + (b * 32) * HW + p;
    float* hout = out + NB * 32 * HW + (b * 32) * HW + p;
#pragma unroll
    for (int j = 0; j < 16; j++) {
        float y0, y1;
        unpack2(ya[j], y0, y1);
        yout[(2 * j) * HW]     = y0;
        yout[(2 * j + 1) * HW] = y1;
    }
#pragma unroll
    for (int o = 0; o < 32; o++) hout[o * HW] = ht[o];
}

extern "C" void kernel_launch(void* const* d_in, const int* in_sizes, int n_in,
                              void* d_out, int out_size) {
    const float* x    = (const float*)d_in[0];
    const float* h    = (const float*)d_in[1];
    const float* w_xz = (const float*)d_in[2];
    const float* b_xz = (const float*)d_in[3];
    const float* w_hz = (const float*)d_in[4];
    const float* b_hz = (const float*)d_in[5];
    const float* w_xr = (const float*)d_in[6];
    const float* b_xr = (const float*)d_in[7];
    const float* w_hr = (const float*)d_in[8];
    const float* b_hr = (const float*)d_in[9];
    const float* w_c  = (const float*)d_in[10];
    const float* b_c  = (const float*)d_in[11];
    const float* w_u  = (const float*)d_in[12];
    const float* b_u  = (const float*)d_in[13];
    const float* w_o  = (const float*)d_in[14];
    const float* b_o  = (const float*)d_in[15];
    float* out = (float*)d_out;

    prep_kernel<<<1, 1024>>>(w_xz, w_hz, w_xr, w_hr, w_c, w_u, w_o,
                             b_xz, b_hz, b_xr, b_hr, b_c, b_u, b_o);

    void *csym = nullptr, *gsym = nullptr;
    cudaGetSymbolAddress(&csym, cAll);
    cudaGetSymbolAddress(&gsym, g_stage);
    cudaMemcpyAsync(csym, gsym, sizeof(float) * (7 * 1024 + 4 * 32),
                    cudaMemcpyDeviceToDevice);

    gru_fused_kernel<<<4096, 128>>>(x, h, out);
}